// round 15
// baseline (speedup 1.0000x reference)
#include <cuda_runtime.h>
#include <cuda_fp16.h>
#include <math.h>

// ConvCaps EM routing (b=8, B=C=32, K=3, s=2, Win=13, Wout=6, 3 EM iters).
// R15: fused persistent kernel at 3 blocks/SM (24 warps/SM).
//  - smem 45.7KB: pose2/ph share one region (pose2 dead after M0); red buffer
//    replaced by smem-atomicAdd reduction into mom; D via shuffle+global atomic.
//  - M0 split into two d-half sweeps (W loaded per p-pair, LDG.64) to fit the
//    ~85-reg cap of __launch_bounds__(256,3).
//  - votes computed once (M0), cached fp16 (85MB, L2-hot within the fused
//    kernel), streamed by the 4 read sweeps with depth-1 prefetch + __ldcg.

#define RP0 (1.0f / 1152.0f)
#define LOG2PI 1.8378770664093453f
typedef unsigned long long ull;

__device__ float g_Wt[147456];        // [oij][q][c][p]
__device__ __half g_votes[42467328];  // [n][xy][oij][h][c][8]
__device__ float g_D0[43264];         // [n][o][13][13]
__device__ float g_D1[43264];
__device__ unsigned g_bar[2];

__global__ void prep_kernel(const float* __restrict__ W) {
    int idx = blockIdx.x * 256 + threadIdx.x;
    if (idx < 147456) {
        int p = idx & 3, c = (idx >> 2) & 31, q = (idx >> 7) & 3;
        int oij = idx >> 9;
        int o = oij / 9, ij = oij - o * 9;
        g_Wt[idx] = W[(((ij * 32 + o) * 32 + c) * 4 + p) * 4 + q];
    }
    if (idx < 43264) { g_D0[idx] = 0.0f; g_D1[idx] = 0.0f; }
    if (idx < 2) g_bar[idx] = 0u;
}

__device__ __forceinline__ ull f2fma(ull a, ull b, ull c) {
    ull d; asm("fma.rn.f32x2 %0, %1, %2, %3;" : "=l"(d) : "l"(a), "l"(b), "l"(c)); return d;
}
__device__ __forceinline__ ull f2mul(ull a, ull b) {
    ull d; asm("mul.rn.f32x2 %0, %1, %2;" : "=l"(d) : "l"(a), "l"(b)); return d;
}
__device__ __forceinline__ ull f2add(ull a, ull b) {
    ull d; asm("add.rn.f32x2 %0, %1, %2;" : "=l"(d) : "l"(a), "l"(b)); return d;
}
__device__ __forceinline__ ull f2pack(float lo, float hi) {
    ull d; asm("mov.b64 %0, {%1, %2};" : "=l"(d) : "f"(lo), "f"(hi)); return d;
}
__device__ __forceinline__ void f2unpack(float& lo, float& hi, ull v) {
    asm("mov.b64 {%0, %1}, %2;" : "=f"(lo), "=f"(hi) : "l"(v));
}
__device__ __forceinline__ unsigned f2h2(ull v) {
    float lo, hi; f2unpack(lo, hi, v);
    unsigned r; asm("cvt.rn.f16x2.f32 %0, %1, %2;" : "=r"(r) : "f"(hi), "f"(lo));
    return r;
}
__device__ __forceinline__ ull h2w(unsigned u) {
    __half2 h = *reinterpret_cast<__half2*>(&u);
    float2 f = __half22float2(h);
    return f2pack(f.x, f.y);
}

// smem float offsets (total 11424 floats = 45696 B -> 3 blocks/SM)
#define SM_PH   0        // 9216: pose2 [oij][qr][2] during M0; ph [oij][c] after
#define SM_A    9216     // 288
#define SM_AD   9504     // 288
#define SM_MOM  9792     // [c][33]: 1056
#define SM_MU   10848    // [c][17]: 544
#define SM_SFAC 11392    // 32
#define SMEM_FLOATS 11424

__global__ void __launch_bounds__(256, 3) fused_kernel(
    const float* __restrict__ x,
    const float* __restrict__ bv_p,
    const float* __restrict__ ba_p,
    const float* __restrict__ lam_p,
    float* __restrict__ out)
{
    extern __shared__ float sm[];
    float* pose2  = sm + SM_PH;     // M0 only
    float* ph_s   = sm + SM_PH;     // alias: born in E0
    float* a_s    = sm + SM_A;
    float* aD_s   = sm + SM_AD;
    float* mom    = sm + SM_MOM;
    float* mu_s   = sm + SM_MU;
    float* sfac_s = sm + SM_SFAC;

    const int xy = blockIdx.x, n = blockIdx.y;
    const int X = xy / 6, Y = xy % 6;
    const int tid = threadIdx.x;
    const int w = tid >> 5;         // warp 0..7 -> positions w*36..w*36+35
    const int c = tid & 31;
    const float* xn = x + n * (544 * 169);
    const int base = (2 * X) * 13 + 2 * Y;

    // ---- load patch ----
    for (int e = tid; e < 512; e += 256) {
        int qr = e & 15, o = e >> 4;
        const float* src = xn + (qr * 32 + o) * 169 + base;
        #pragma unroll
        for (int i = 0; i < 3; i++)
            #pragma unroll
            for (int j = 0; j < 3; j++) {
                float v = src[i * 13 + j];
                int off = (o * 9 + i * 3 + j) * 32 + qr * 2;
                pose2[off] = v; pose2[off + 1] = v;
            }
    }
    for (int e = tid; e < 288; e += 256) {
        int o = e / 9, ij = e - o * 9;
        float av = xn[(512 + o) * 169 + base + (ij / 3) * 13 + (ij % 3)];
        a_s[e] = av;
        aD_s[e] = av * RP0;
    }
    __syncthreads();

    const float bv = bv_p[0], ba = ba_p[0], lam = lam_p[0];
    uint4* vb = (uint4*)g_votes + (((n * 36 + xy) * 288 + w * 36) * 2) * 32 + c;
    const ull* wbh = (const ull*)g_Wt + (w * 36 * 4) * 64 + c * 2;  // + h

    for (int it = 0; it < 3; it++) {
        // ---- zero mom ----
        for (int s = tid; s < 1056; s += 256) mom[s] = 0.0f;
        __syncthreads();

        if (it == 0) {
            // ====== M0: two d-half sweeps (low reg pressure) ======
            #pragma unroll 1
            for (int h = 0; h < 2; h++) {
                ull m1[4], m2[4];
                #pragma unroll
                for (int r = 0; r < 4; r++) { m1[r] = 0ull; m2[r] = 0ull; }
                float sumr = 0.0f;
                #pragma unroll 2
                for (int k = 0; k < 36; k++) {
                    int oij = w * 36 + k;
                    const ull* wk = wbh + (k * 4) * 64 + h;
                    ull wq0 = wk[0], wq1 = wk[64], wq2 = wk[128], wq3 = wk[192];
                    float rh = aD_s[oij];
                    sumr += rh;
                    ull rh2 = f2pack(rh, rh);
                    const ulonglong2* pb2 = (const ulonglong2*)(pose2 + oij * 32);
                    ull v[4];
                    {
                        ulonglong2 pA = pb2[0], pB = pb2[1];
                        v[0] = f2mul(wq0, pA.x); v[1] = f2mul(wq0, pA.y);
                        v[2] = f2mul(wq0, pB.x); v[3] = f2mul(wq0, pB.y);
                    }
                    {
                        ulonglong2 pA = pb2[2], pB = pb2[3];
                        v[0] = f2fma(wq1, pA.x, v[0]); v[1] = f2fma(wq1, pA.y, v[1]);
                        v[2] = f2fma(wq1, pB.x, v[2]); v[3] = f2fma(wq1, pB.y, v[3]);
                    }
                    {
                        ulonglong2 pA = pb2[4], pB = pb2[5];
                        v[0] = f2fma(wq2, pA.x, v[0]); v[1] = f2fma(wq2, pA.y, v[1]);
                        v[2] = f2fma(wq2, pB.x, v[2]); v[3] = f2fma(wq2, pB.y, v[3]);
                    }
                    {
                        ulonglong2 pA = pb2[6], pB = pb2[7];
                        v[0] = f2fma(wq3, pA.x, v[0]); v[1] = f2fma(wq3, pA.y, v[1]);
                        v[2] = f2fma(wq3, pB.x, v[2]); v[3] = f2fma(wq3, pB.y, v[3]);
                    }
                    uint4 s4;
                    s4.x = f2h2(v[0]); s4.y = f2h2(v[1]);
                    s4.z = f2h2(v[2]); s4.w = f2h2(v[3]);
                    vb[k * 64 + h * 32] = s4;
                    #pragma unroll
                    for (int r = 0; r < 4; r++) {
                        ull t = f2mul(rh2, v[r]);
                        m1[r] = f2add(m1[r], t);
                        m2[r] = f2fma(t, v[r], m2[r]);
                    }
                }
                // atomic reduce: d = 8h + {r, 4+r}
                #pragma unroll
                for (int r = 0; r < 4; r++) {
                    float lo, hi;
                    f2unpack(lo, hi, m1[r]);
                    atomicAdd(&mom[c * 33 + 8 * h + r], lo);
                    atomicAdd(&mom[c * 33 + 8 * h + 4 + r], hi);
                    f2unpack(lo, hi, m2[r]);
                    atomicAdd(&mom[c * 33 + 16 + 8 * h + r], lo);
                    atomicAdd(&mom[c * 33 + 16 + 8 * h + 4 + r], hi);
                }
                if (h == 0) atomicAdd(&mom[c * 33 + 32], sumr);
            }
        } else {
            // ====== M-read: stream cached votes ======
            ull m1a[4], m1b[4], m2a[4], m2b[4];
            #pragma unroll
            for (int r = 0; r < 4; r++) { m1a[r]=0ull; m1b[r]=0ull; m2a[r]=0ull; m2b[r]=0ull; }
            float sumr = 0.0f;
            uint4 a0 = __ldcg(vb), a1 = __ldcg(vb + 32);
            #pragma unroll 4
            for (int k = 0; k < 36; k++) {
                uint4 b0 = a0, b1 = a1;
                if (k < 35) { b0 = __ldcg(vb + (k + 1) * 64); b1 = __ldcg(vb + (k + 1) * 64 + 32); }
                int oij = w * 36 + k;
                float rh = ph_s[oij * 32 + c] * aD_s[oij];
                sumr += rh;
                ull rh2 = f2pack(rh, rh);
                ull sv0[4], sv1[4];
                sv0[0] = h2w(a0.x); sv0[1] = h2w(a0.y); sv0[2] = h2w(a0.z); sv0[3] = h2w(a0.w);
                sv1[0] = h2w(a1.x); sv1[1] = h2w(a1.y); sv1[2] = h2w(a1.z); sv1[3] = h2w(a1.w);
                #pragma unroll
                for (int r = 0; r < 4; r++) {
                    ull t0 = f2mul(rh2, sv0[r]);
                    m1a[r] = f2add(m1a[r], t0);
                    m2a[r] = f2fma(t0, sv0[r], m2a[r]);
                    ull t1 = f2mul(rh2, sv1[r]);
                    m1b[r] = f2add(m1b[r], t1);
                    m2b[r] = f2fma(t1, sv1[r], m2b[r]);
                }
                a0 = b0; a1 = b1;
            }
            #pragma unroll
            for (int r = 0; r < 4; r++) {
                float lo, hi;
                f2unpack(lo, hi, m1a[r]);
                atomicAdd(&mom[c * 33 + r], lo);
                atomicAdd(&mom[c * 33 + 4 + r], hi);
                f2unpack(lo, hi, m1b[r]);
                atomicAdd(&mom[c * 33 + 8 + r], lo);
                atomicAdd(&mom[c * 33 + 12 + r], hi);
                f2unpack(lo, hi, m2a[r]);
                atomicAdd(&mom[c * 33 + 16 + r], lo);
                atomicAdd(&mom[c * 33 + 20 + r], hi);
                f2unpack(lo, hi, m2b[r]);
                atomicAdd(&mom[c * 33 + 24 + r], lo);
                atomicAdd(&mom[c * 33 + 28 + r], hi);
            }
            atomicAdd(&mom[c * 33 + 32], sumr);
        }
        __syncthreads();

        // ================= stats =================
        if (tid < 32) {
            const float* mm = mom + tid * 33;
            float R = mm[32], invR = 1.0f / R, cs = 0.0f;
            #pragma unroll
            for (int d = 0; d < 16; d++) {
                float m  = mm[d] * invR;
                float sg = fmaf(-m, m, mm[16 + d] * invR);
                mu_s[tid * 17 + d] = m;
                cs += __logf(sg);
            }
            float cost = R * fmaf(16.0f, bv, cs);
            float act  = 1.0f / (1.0f + __expf(lam * (cost - ba)));
            if (it == 2) {
                float* on = out + (long)n * 19584 + xy;
                #pragma unroll
                for (int d = 0; d < 16; d++)
                    on[(tid * 16 + d) * 36] = mu_s[tid * 17 + d];
                on[(512 + tid) * 36] = act;
            } else {
                sfac_s[tid] = act * __expf(-0.5f * fmaf(16.0f, LOG2PI, cs));
            }
        }
        if (it == 2) return;
        __syncthreads();

        // ====== E: stream votes; ph -> smem (overwrites dead pose2); D atomic ======
        {
            float sf = sfac_s[c];
            ull nmu0[4], nmu1[4];
            #pragma unroll
            for (int r = 0; r < 4; r++) {
                nmu0[r] = f2pack(-mu_s[c * 17 + r],     -mu_s[c * 17 + 4 + r]);
                nmu1[r] = f2pack(-mu_s[c * 17 + 8 + r], -mu_s[c * 17 + 12 + r]);
            }
            float* Dg = (it == 0) ? g_D0 : g_D1;
            uint4 a0 = __ldcg(vb), a1 = __ldcg(vb + 32);
            #pragma unroll 4
            for (int k = 0; k < 36; k++) {
                uint4 b0 = a0, b1 = a1;
                if (k < 35) { b0 = __ldcg(vb + (k + 1) * 64); b1 = __ldcg(vb + (k + 1) * 64 + 32); }
                int oij = w * 36 + k;
                ull sa, sb;
                { ull d0 = f2add(h2w(a0.x), nmu0[0]); sa = f2mul(d0, d0);
                  ull d1 = f2add(h2w(a0.y), nmu0[1]); sb = f2mul(d1, d1); }
                { ull d0 = f2add(h2w(a0.z), nmu0[2]); sa = f2fma(d0, d0, sa);
                  ull d1 = f2add(h2w(a0.w), nmu0[3]); sb = f2fma(d1, d1, sb); }
                { ull d0 = f2add(h2w(a1.x), nmu1[0]); sa = f2fma(d0, d0, sa);
                  ull d1 = f2add(h2w(a1.y), nmu1[1]); sb = f2fma(d1, d1, sb); }
                { ull d0 = f2add(h2w(a1.z), nmu1[2]); sa = f2fma(d0, d0, sa);
                  ull d1 = f2add(h2w(a1.w), nmu1[3]); sb = f2fma(d1, d1, sb); }
                float slo, shi; f2unpack(slo, shi, f2add(sa, sb));
                float ph = sf * __expf(-(slo + shi));
                // kperm=[0,2,1] self-inverse: permuted slot is in this warp's range
                int o = oij / 9, ij = oij - o * 9;
                int i2 = ij / 3, j2 = ij - i2 * 3;
                int ip = (3 - i2) % 3, jp = (3 - j2) % 3;
                ph_s[(o * 9 + ip * 3 + jp) * 32 + c] = ph;
                float T = ph;
                #pragma unroll
                for (int s = 16; s > 0; s >>= 1) T += __shfl_xor_sync(0xffffffffu, T, s);
                if (c == 0)
                    atomicAdd(&Dg[(n * 32 + o) * 169 + (2 * X + ip) * 13 + (2 * Y + jp)], T);
                a0 = b0; a1 = b1;
            }
        }
        __syncthreads();

        // ---- grid barrier (288 blocks <= 3/SM x 148 co-resident) ----
        if (tid == 0) {
            __threadfence();
            atomicAdd(&g_bar[it], 1u);
            while (*((volatile unsigned*)&g_bar[it]) < 288u) { __nanosleep(32); }
        }
        __syncthreads();

        // ---- aD pass ----
        for (int e = tid; e < 288; e += 256) {
            int o = e / 9, ij = e - o * 9;
            float* Dg = (it == 0) ? g_D0 : g_D1;
            float Dv = __ldcg(&Dg[(n * 32 + o) * 169 + (2 * X + ij / 3) * 13 + (2 * Y + ij % 3)]);
            aD_s[e] = __fdividef(a_s[e], Dv);
        }
        __syncthreads();
    }
}

extern "C" void kernel_launch(void* const* d_in, const int* in_sizes, int n_in,
                              void* d_out, int out_size) {
    const float* x   = (const float*)d_in[0];
    const float* W   = (const float*)d_in[1];
    const float* bv  = (const float*)d_in[2];
    const float* ba  = (const float*)d_in[3];
    const float* lam = (const float*)d_in[4];
    float* out = (float*)d_out;

    const int smem = SMEM_FLOATS * 4;   // 45696 B
    cudaFuncSetAttribute(fused_kernel, cudaFuncAttributeMaxDynamicSharedMemorySize, smem);

    prep_kernel<<<576, 256>>>(W);
    fused_kernel<<<dim3(36, 8), 256, smem>>>(x, bv, ba, lam, out);
}